// round 1
// baseline (speedup 1.0000x reference)
#include <cuda_runtime.h>

// SLayer: out[b,n] = sum_p exp(-(s0*(c0-x)^2 + s1*(c1-y)^2)) * mask[b,p]
// B=64, P=16384, N=64, D=2
constexpr int B_ = 64;
constexpr int P_ = 16384;
constexpr int N_ = 64;
constexpr int CHUNK = 2048;           // points per block
constexpr int SPLITS = P_ / CHUNK;    // 8
constexpr int NPW = 8;                // n-values per warp (8 warps * 8 = 64)

__global__ void zero_out_kernel(float* out) {
    out[blockIdx.x * blockDim.x + threadIdx.x] = 0.0f;
}

__device__ __forceinline__ float ex2_approx(float x) {
    float r;
    asm("ex2.approx.ftz.f32 %0, %1;" : "=f"(r) : "f"(x));
    return r;
}

__global__ __launch_bounds__(256, 4)
void rbf_pool_kernel(const float* __restrict__ batch,
                     const float* __restrict__ mask,
                     const float* __restrict__ centers,
                     const float* __restrict__ sharp,
                     float* __restrict__ out) {
    const int b    = blockIdx.x;
    const int s    = blockIdx.y;
    const int warp = threadIdx.x >> 5;
    const int lane = threadIdx.x & 31;
    const int n0   = warp * NPW;

    // exp(-expo) = 2^(L*expo), L = -log2(e). Expand quadratic, fold L into all
    // per-n constants:
    //   e = A0*x^2 + A1*y^2 + Bx*x + By*y + C
    const float L = -1.4426950408889634f;

    float A0[NPW], A1[NPW], Bx[NPW], By[NPW], Cc[NPW], acc[NPW];
#pragma unroll
    for (int i = 0; i < NPW; i++) {
        const int n = n0 + i;
        const float c0 = centers[n * 2 + 0];
        const float c1 = centers[n * 2 + 1];
        const float s0 = sharp[n * 2 + 0];
        const float s1 = sharp[n * 2 + 1];
        A0[i] = L * s0;
        A1[i] = L * s1;
        Bx[i] = -2.0f * L * s0 * c0;
        By[i] = -2.0f * L * s1 * c1;
        Cc[i] = L * (s0 * c0 * c0 + s1 * c1 * c1);
        acc[i] = 0.0f;
    }

    const float2* pts = reinterpret_cast<const float2*>(batch) + (size_t)b * P_ + s * CHUNK;
    const float*  msk = mask + (size_t)b * P_ + s * CHUNK;

#pragma unroll 4
    for (int p = lane; p < CHUNK; p += 32) {
        const float2 xy = pts[p];
        const float  mm = msk[p];
        const float x2 = xy.x * xy.x;
        const float y2 = xy.y * xy.y;
#pragma unroll
        for (int i = 0; i < NPW; i++) {
            float e = fmaf(A0[i], x2, Cc[i]);
            e = fmaf(A1[i], y2, e);
            e = fmaf(Bx[i], xy.x, e);
            e = fmaf(By[i], xy.y, e);
            const float w = ex2_approx(e);
            acc[i] = fmaf(w, mm, acc[i]);
        }
    }

    // warp tree-reduce each accumulator, lane 0 commits
#pragma unroll
    for (int i = 0; i < NPW; i++) {
        float v = acc[i];
#pragma unroll
        for (int o = 16; o > 0; o >>= 1)
            v += __shfl_xor_sync(0xFFFFFFFFu, v, o);
        if (lane == 0)
            atomicAdd(&out[b * N_ + n0 + i], v);
    }
}

extern "C" void kernel_launch(void* const* d_in, const int* in_sizes, int n_in,
                              void* d_out, int out_size) {
    const float* batch   = (const float*)d_in[0];  // [64,16384,2]
    const float* mask    = (const float*)d_in[1];  // [64,16384]
    const float* centers = (const float*)d_in[2];  // [64,2]
    const float* sharp   = (const float*)d_in[3];  // [64,2]
    float* out = (float*)d_out;                    // [64,64]

    zero_out_kernel<<<16, 256>>>(out);             // 4096 elems
    dim3 grid(B_, SPLITS);
    rbf_pool_kernel<<<grid, 256>>>(batch, mask, centers, sharp, out);
}

// round 2
// speedup vs baseline: 1.1088x; 1.1088x over previous
#include <cuda_runtime.h>
#include <cstdint>

// SLayer: out[b,n] = sum_p exp(-(s0*(c0-x)^2 + s1*(c1-y)^2)) * mask[b,p]
// B=64, P=16384, N=64, D=2
constexpr int B_ = 64;
constexpr int P_ = 16384;
constexpr int N_ = 64;
constexpr int CHUNK = 2048;           // points per block
constexpr int SPLITS = P_ / CHUNK;    // 8 -> grid 512 = one wave @ 4 blocks/SM
constexpr int NPW = 8;                // n per warp (8 warps * 8 = 64)
constexpr int NPAIR = NPW / 2;        // 4 packed pairs

__global__ void zero_out_kernel(float* out) {
    out[blockIdx.x * blockDim.x + threadIdx.x] = 0.0f;
}

__device__ __forceinline__ float ex2_approx(float x) {
    float r;
    asm("ex2.approx.ftz.f32 %0, %1;" : "=f"(r) : "f"(x));
    return r;
}

__device__ __forceinline__ uint64_t pack2(float lo, float hi) {
    uint64_t d;
    asm("mov.b64 %0, {%1, %2};" : "=l"(d) : "f"(lo), "f"(hi));
    return d;
}

__device__ __forceinline__ void unpack2(float& lo, float& hi, uint64_t v) {
    asm("mov.b64 {%0, %1}, %2;" : "=f"(lo), "=f"(hi) : "l"(v));
}

__device__ __forceinline__ uint64_t fma2(uint64_t a, uint64_t b, uint64_t c) {
    uint64_t d;
    asm("fma.rn.f32x2 %0, %1, %2, %3;" : "=l"(d) : "l"(a), "l"(b), "l"(c));
    return d;
}

__global__ __launch_bounds__(256, 4)
void rbf_pool_kernel(const float* __restrict__ batch,
                     const float* __restrict__ mask,
                     const float* __restrict__ centers,
                     const float* __restrict__ sharp,
                     float* __restrict__ out) {
    const int b    = blockIdx.x;
    const int s    = blockIdx.y;
    const int warp = threadIdx.x >> 5;
    const int lane = threadIdx.x & 31;
    const int n0   = warp * NPW;

    // exp(-expo) = 2^(L*expo), L = -log2(e). Expand quadratic:
    //   e_n = A0*x^2 + A1*y^2 + Bx*x + By*y + C  (all consts fold L)
    const float L = -1.4426950408889634f;

    uint64_t A0p[NPAIR], A1p[NPAIR], Bxp[NPAIR], Byp[NPAIR], Cp[NPAIR], acc[NPAIR];
#pragma unroll
    for (int j = 0; j < NPAIR; j++) {
        float a0[2], a1[2], bx[2], by[2], cc[2];
#pragma unroll
        for (int h = 0; h < 2; h++) {
            const int n = n0 + 2 * j + h;
            const float c0 = centers[n * 2 + 0];
            const float c1 = centers[n * 2 + 1];
            const float s0 = sharp[n * 2 + 0];
            const float s1 = sharp[n * 2 + 1];
            a0[h] = L * s0;
            a1[h] = L * s1;
            bx[h] = -2.0f * L * s0 * c0;
            by[h] = -2.0f * L * s1 * c1;
            cc[h] = L * (s0 * c0 * c0 + s1 * c1 * c1);
        }
        A0p[j] = pack2(a0[0], a0[1]);
        A1p[j] = pack2(a1[0], a1[1]);
        Bxp[j] = pack2(bx[0], bx[1]);
        Byp[j] = pack2(by[0], by[1]);
        Cp[j]  = pack2(cc[0], cc[1]);
        acc[j] = 0ull;
    }

    const float2* pts = reinterpret_cast<const float2*>(batch) + (size_t)b * P_ + s * CHUNK;
    const float*  msk = mask + (size_t)b * P_ + s * CHUNK;

#pragma unroll 2
    for (int p = lane; p < CHUNK; p += 32) {
        const float2 xy = pts[p];
        const float  mm = msk[p];
        const float x2 = xy.x * xy.x;
        const float y2 = xy.y * xy.y;
        const uint64_t xb  = pack2(xy.x, xy.x);
        const uint64_t yb  = pack2(xy.y, xy.y);
        const uint64_t x2b = pack2(x2, x2);
        const uint64_t y2b = pack2(y2, y2);
        const uint64_t mb  = pack2(mm, mm);
#pragma unroll
        for (int j = 0; j < NPAIR; j++) {
            uint64_t e = fma2(A0p[j], x2b, Cp[j]);
            e = fma2(A1p[j], y2b, e);
            e = fma2(Bxp[j], xb, e);
            e = fma2(Byp[j], yb, e);
            float elo, ehi;
            unpack2(elo, ehi, e);
            const uint64_t w = pack2(ex2_approx(elo), ex2_approx(ehi));
            acc[j] = fma2(w, mb, acc[j]);
        }
    }

    // warp tree-reduce each accumulator pair, lane 0 commits
#pragma unroll
    for (int j = 0; j < NPAIR; j++) {
        float vlo, vhi;
        unpack2(vlo, vhi, acc[j]);
#pragma unroll
        for (int o = 16; o > 0; o >>= 1) {
            vlo += __shfl_xor_sync(0xFFFFFFFFu, vlo, o);
            vhi += __shfl_xor_sync(0xFFFFFFFFu, vhi, o);
        }
        if (lane == 0) {
            atomicAdd(&out[b * N_ + n0 + 2 * j + 0], vlo);
            atomicAdd(&out[b * N_ + n0 + 2 * j + 1], vhi);
        }
    }
}

extern "C" void kernel_launch(void* const* d_in, const int* in_sizes, int n_in,
                              void* d_out, int out_size) {
    const float* batch   = (const float*)d_in[0];  // [64,16384,2]
    const float* mask    = (const float*)d_in[1];  // [64,16384]
    const float* centers = (const float*)d_in[2];  // [64,2]
    const float* sharp   = (const float*)d_in[3];  // [64,2]
    float* out = (float*)d_out;                    // [64,64]

    zero_out_kernel<<<16, 256>>>(out);             // 4096 elems
    dim3 grid(B_, SPLITS);
    rbf_pool_kernel<<<grid, 256>>>(batch, mask, centers, sharp, out);
}